// round 10
// baseline (speedup 1.0000x reference)
#include <cuda_runtime.h>
#include <cuda_fp16.h>
#include <stdint.h>
#include <math.h>

// ================= problem constants =================
#define Bsz   32
#define NPIC  4
#define CCH   3
#define Him   224
#define Wim   224
#define PPs   16
#define HPn   14
#define SSn   196
#define DDn   768
#define ROWS  (Bsz*NPIC*SSn)   // 25088
#define QROWS (Bsz*SSn)        // 6272
#define NBat  (Bsz*NPIC)       // 128
#define KPAD  256

// ================= device scratch =================
__device__ __align__(1024) __half g_p  [ROWS*DDn];
__device__ __align__(1024) __half g_wt [6*DDn*DDn];   // 0=W1 rowmajor,1=WqT,2=WkT,3=WvT,4=Wo1T,5=Wo2T
__device__ __align__(1024) __half g_wc [3*DDn*DDn];   // composite (W1Wq)T,(W1Wk)T,(W1Wv)T
__device__ __align__(1024) float  g_bc [3*DDn];       // composite biases q,k,v
__device__ __align__(1024) __half g_q  [QROWS*DDn];
__device__ __align__(1024) __half g_k  [ROWS*DDn];
__device__ __align__(1024) __half g_v  [ROWS*DDn];
__device__ __align__(1024) __half g_vt [NBat*DDn*KPAD];
__device__ __align__(1024) __half g_at [NBat*SSn*KPAD];
__device__ __align__(1024) __half g_wv [ROWS*DDn];
__device__ __align__(1024) __half g_t  [ROWS*DDn];

// ================= helpers =================
__device__ __forceinline__ uint32_t smem_u32(const void* p){
    uint32_t a;
    asm("{ .reg .u64 t; cvta.to.shared.u64 t, %1; cvt.u32.u64 %0, t; }" : "=r"(a) : "l"(p));
    return a;
}
#define SWZ128(o) ((o) ^ (((o) >> 3) & 0x70))

__device__ __forceinline__ void cp16(uint32_t dst, const void* src, int nbytes){
    asm volatile("cp.async.cg.shared.global [%0], [%1], 16, %2;"
                 :: "r"(dst), "l"(src), "r"(nbytes) : "memory");
}
__device__ __forceinline__ void cp_commit(){ asm volatile("cp.async.commit_group;" ::: "memory"); }
__device__ __forceinline__ void cp_wait2(){  asm volatile("cp.async.wait_group 2;" ::: "memory"); }

__device__ __forceinline__ void ldsm4(uint32_t& r0,uint32_t& r1,uint32_t& r2,uint32_t& r3,uint32_t a){
    asm volatile("ldmatrix.sync.aligned.m8n8.x4.shared.b16 {%0,%1,%2,%3}, [%4];"
        : "=r"(r0),"=r"(r1),"=r"(r2),"=r"(r3) : "r"(a));
}
__device__ __forceinline__ void mma16816(float* c, const uint32_t* a, const uint32_t* b){
    asm volatile("mma.sync.aligned.m16n8k16.row.col.f32.f16.f16.f32 "
        "{%0,%1,%2,%3}, {%4,%5,%6,%7}, {%8,%9}, {%0,%1,%2,%3};"
        : "+f"(c[0]),"+f"(c[1]),"+f"(c[2]),"+f"(c[3])
        : "r"(a[0]),"r"(a[1]),"r"(a[2]),"r"(a[3]), "r"(b[0]),"r"(b[1]));
}

// ================= patchify -> fp16 =================
__global__ void patchify_h(const float* __restrict__ x, __half* __restrict__ p)
{
    long long idx = (long long)blockIdx.x * blockDim.x + threadIdx.x;
    long long total = (long long)ROWS * DDn;
    if (idx >= total) return;
    int d    = (int)(idx % DDn);
    int rest = (int)(idx / DDn);
    int s    = rest % SSn;
    int pic  = rest / SSn;
    int c  = d >> 8;
    int rm = d & 255;
    int ph = rm >> 4;
    int pw = rm & 15;
    int i = s / HPn, j = s % HPn;
    long long src = (((long long)pic * CCH + c) * Him + (i*PPs + ph)) * Wim + (j*PPs + pw);
    p[idx] = __float2half(x[src]);
}

// ================= weight transpose -> fp16 (wt[n][k] = W[k][n]) ==========
__global__ void wtrans_h(const float* __restrict__ W, __half* __restrict__ wt)
{
    int idx = blockIdx.x * blockDim.x + threadIdx.x;
    if (idx >= DDn*DDn) return;
    int n = idx / DDn, k = idx % DDn;
    wt[idx] = __float2half(W[k*DDn + n]);
}
// ================= plain convert -> fp16 (row-major) ======================
__global__ void wconv_h(const float* __restrict__ W, __half* __restrict__ wh)
{
    int idx = blockIdx.x * blockDim.x + threadIdx.x;
    if (idx >= DDn*DDn) return;
    wh[idx] = __float2half(W[idx]);
}
// ================= composite bias: bc[n] = sum_k b1[k]*Wx[k][n] + bx[n] ====
__global__ void bias_comp(const float* __restrict__ b1, const float* __restrict__ Wx,
                          const float* __restrict__ bx, float* __restrict__ bc)
{
    int n = blockIdx.x * blockDim.x + threadIdx.x;
    if (n >= DDn) return;
    float s = bx[n];
    for (int k = 0; k < DDn; k++) s += b1[k] * Wx[k*DDn + n];
    bc[n] = s;
}

// ================= V transpose (fp16, pad 256) =================
__global__ void vtrans_h(const __half* __restrict__ V, __half* __restrict__ vt)
{
    __shared__ __half tile[32][33];
    int z  = blockIdx.z;
    int d0 = blockIdx.x * 32;
    int s0 = blockIdx.y * 32;
    int tx = threadIdx.x, ty = threadIdx.y;
    for (int sy = ty; sy < 32; sy += 8) {
        int s = s0 + sy, d = d0 + tx;
        tile[sy][tx] = (s < SSn) ? V[((long long)z*SSn + s)*DDn + d] : __float2half(0.f);
    }
    __syncthreads();
    for (int dy = ty; dy < 32; dy += 8) {
        int d = d0 + dy, s = s0 + tx;
        vt[((long long)z*DDn + d)*KPAD + s] = tile[tx][dy];
    }
}

// ================= mma.sync fp16 GEMM (128x256 tile, 3-stage pipeline) =====
#define BMt 128
#define BNt 256
#define BKt 64
#define NTHR 256
#define TILEA 16384
#define TILEB 32768
#define STGSZ (TILEA + TILEB)
#define DSM   (3*STGSZ + 1024)

__global__ void __launch_bounds__(NTHR)
mm_gemm(const __half* __restrict__ A, const __half* __restrict__ B,
        const float* __restrict__ bias,
        float* __restrict__ Cf, __half* __restrict__ Ch, __half* __restrict__ Smx,
        int M, int Nvalid, int K, int ldA, int ldB, int ldC,
        long long sA, long long sB, long long sC, int zdivA,
        float alpha, int relu, int remapA)
{
    extern __shared__ char dsm[];
    uint32_t dyn  = smem_u32(dsm);
    uint32_t base = (dyn + 1023u) & ~1023u;
    const uint32_t stg[3] = { base, base + STGSZ, base + 2*STGSZ };

    const int t = threadIdx.x, lane = t & 31, w = t >> 5;
    const int wm = w & 1, wn = w >> 1;
    const int z = blockIdx.z;
    const int m0 = blockIdx.y * BMt;
    const int n0 = blockIdx.x * BNt;

    const __half* Az = A + (long long)(z / zdivA) * sA;
    const __half* Bz = B + (long long)z * sB;
    float* Cfz = Cf ? Cf + (long long)z * sC : nullptr;
    __half* Chz = Ch ? Ch + (long long)z * sC : nullptr;
    __half* Smxz = Smx ? Smx + (long long)z * sC : nullptr;

    float acc[4][8][4];
#pragma unroll
    for (int a = 0; a < 4; a++)
#pragma unroll
        for (int b = 0; b < 8; b++)
#pragma unroll
            for (int c = 0; c < 4; c++) acc[a][b][c] = 0.f;

    const int ITERS = K / BKt;

#define LOAD_STAGE(ITN, BUF)                                                         \
    {                                                                                \
        int k0 = (ITN) * BKt;                                                        \
        _Pragma("unroll")                                                            \
        for (int j = 0; j < 4; j++) {                                                \
            int flat = t + j*256;                                                    \
            int row = flat >> 3, cc = flat & 7;                                      \
            uint32_t so = SWZ128((uint32_t)(row*128 + cc*16));                       \
            int gr = m0 + row;                                                       \
            int ok = gr < M;                                                         \
            long long pr = 0;                                                        \
            if (ok) pr = remapA ? (long long)gr + (gr/SSn)*(NPIC*SSn - SSn)          \
                                : (long long)gr;                                     \
            cp16(stg[BUF] + so, Az + pr*ldA + k0 + cc*8, ok ? 16 : 0);               \
        }                                                                            \
        _Pragma("unroll")                                                            \
        for (int j = 0; j < 8; j++) {                                                \
            int flat = t + j*256;                                                    \
            int row = flat >> 3, cc = flat & 7;                                      \
            uint32_t so = SWZ128((uint32_t)(row*128 + cc*16));                       \
            int gn = n0 + row;                                                       \
            int okb = gn < Nvalid;                                                   \
            long long pn = okb ? gn : 0;                                             \
            cp16(stg[BUF] + TILEA + so, Bz + pn*ldB + k0 + cc*8, okb ? 16 : 0);      \
        }                                                                            \
    }

    LOAD_STAGE(0, 0); cp_commit();
    LOAD_STAGE(1, 1); cp_commit();

    const int rl = lane & 15, hh = lane >> 4;

    for (int itn = 0; itn < ITERS; itn++) {
        int buf = itn % 3;
        if (itn + 2 < ITERS) { int nb = (itn + 2) % 3; LOAD_STAGE(itn + 2, nb); }
        cp_commit();
        cp_wait2();
        __syncthreads();

        uint32_t sA_ = stg[buf], sB_ = stg[buf] + TILEA;
#pragma unroll
        for (int ks = 0; ks < 4; ks++) {
            int c = ks*2 + hh;
            uint32_t af[4][4], bf[8][2];
#pragma unroll
            for (int mt = 0; mt < 4; mt++) {
                int row = wm*64 + mt*16 + rl;
                uint32_t so = SWZ128((uint32_t)(row*128 + c*16));
                ldsm4(af[mt][0], af[mt][1], af[mt][2], af[mt][3], sA_ + so);
            }
#pragma unroll
            for (int bt = 0; bt < 4; bt++) {
                int row = wn*64 + bt*16 + rl;
                uint32_t so = SWZ128((uint32_t)(row*128 + c*16));
                uint32_t r0, r1, r2, r3;
                ldsm4(r0, r1, r2, r3, sB_ + so);
                bf[bt*2][0]   = r0;  bf[bt*2][1]   = r2;
                bf[bt*2+1][0] = r1;  bf[bt*2+1][1] = r3;
            }
#pragma unroll
            for (int mt = 0; mt < 4; mt++)
#pragma unroll
                for (int nt = 0; nt < 8; nt++)
                    mma16816(acc[mt][nt], af[mt], bf[nt]);
        }
    }

    const int r0l = lane >> 2, cl = (lane & 3) * 2;

    if (Smx) {
        // ---- fused softmax epilogue ----
        __half* stage = (__half*)(dsm + (base - dyn));
        __syncthreads();
#pragma unroll
        for (int mt = 0; mt < 4; mt++)
#pragma unroll
            for (int nt = 0; nt < 8; nt++) {
                int col = wn*64 + nt*8 + cl;
#pragma unroll
                for (int half = 0; half < 2; half++) {
                    int r = wm*64 + mt*16 + r0l + half*8;
                    stage[r*256 + col]     = __float2half(acc[mt][nt][half*2 + 0] * alpha);
                    stage[r*256 + col + 1] = __float2half(acc[mt][nt][half*2 + 1] * alpha);
                }
            }
        __syncthreads();
        for (int rr = 0; rr < 16; rr++) {
            int r = w*16 + rr;
            int gr = m0 + r;
            if (gr >= M) continue;
            float v[7];
            float mx = -INFINITY;
#pragma unroll
            for (int i = 0; i < 7; i++) {
                int c = lane + i*32;
                v[i] = (c < SSn) ? __half2float(stage[r*256 + c]) : -INFINITY;
                mx = fmaxf(mx, v[i]);
            }
#pragma unroll
            for (int o = 16; o > 0; o >>= 1) mx = fmaxf(mx, __shfl_xor_sync(0xffffffffu, mx, o));
            float sum = 0.f;
#pragma unroll
            for (int i = 0; i < 7; i++) {
                int c = lane + i*32;
                if (c < SSn) { v[i] = __expf(v[i] - mx); sum += v[i]; } else v[i] = 0.f;
            }
#pragma unroll
            for (int o = 16; o > 0; o >>= 1) sum += __shfl_xor_sync(0xffffffffu, sum, o);
            float inv = 1.f / sum;
            __half* orow = Smxz + (long long)gr * KPAD;
#pragma unroll
            for (int i = 0; i < 8; i++) {
                int c = lane + i*32;
                float val = (i < 7 && c < SSn) ? v[i] * inv : 0.f;
                orow[c] = __float2half(val);
            }
        }
        return;
    }

    // ---- normal epilogue ----
#pragma unroll
    for (int mt = 0; mt < 4; mt++) {
#pragma unroll
        for (int nt = 0; nt < 8; nt++) {
            int gc = n0 + wn*64 + nt*8 + cl;
#pragma unroll
            for (int half = 0; half < 2; half++) {
                int gr = m0 + wm*64 + mt*16 + r0l + half*8;
                if (gr >= M) continue;
                float v0 = acc[mt][nt][half*2 + 0] * alpha;
                float v1 = acc[mt][nt][half*2 + 1] * alpha;
                if (bias) { v0 += __ldg(bias + gc); v1 += __ldg(bias + gc + 1); }
                if (relu) { v0 = fmaxf(v0, 0.f); v1 = fmaxf(v1, 0.f); }
                long long o = (long long)gr * ldC + gc;
                if (gc < Nvalid) {
                    if (Cfz) Cfz[o] = v0;
                    if (Chz) Chz[o] = __float2half(v0);
                }
                if (gc + 1 < Nvalid) {
                    if (Cfz) Cfz[o+1] = v1;
                    if (Chz) Chz[o+1] = __float2half(v1);
                }
            }
        }
    }
}

// ================= host side =================
static void gemm(const __half* A, const __half* B, const float* bias,
                 float* Cf, __half* Ch, __half* Smx,
                 int M, int Nvalid, int K, int ldA, int ldB, int ldC,
                 long long sA, long long sB, long long sC, int zdivA, int nz,
                 float alpha, int relu, int remapA)
{
    dim3 g((Nvalid + BNt - 1)/BNt, (M + BMt - 1)/BMt, nz);
    mm_gemm<<<g, NTHR, DSM>>>(A, B, bias, Cf, Ch, Smx,
                              M, Nvalid, K, ldA, ldB, ldC, sA, sB, sC,
                              zdivA, alpha, relu, remapA);
}

extern "C" void kernel_launch(void* const* d_in, const int* in_sizes, int n_in,
                              void* d_out, int out_size)
{
    const float* x   = (const float*)d_in[0];
    const float* W1  = (const float*)d_in[1];
    const float* b1  = (const float*)d_in[2];
    const float* Wq  = (const float*)d_in[3];
    const float* bq  = (const float*)d_in[4];
    const float* Wk  = (const float*)d_in[5];
    const float* bk  = (const float*)d_in[6];
    const float* Wv  = (const float*)d_in[7];
    const float* bv  = (const float*)d_in[8];
    const float* Wo1 = (const float*)d_in[9];
    const float* bo1 = (const float*)d_in[10];
    const float* Wo2 = (const float*)d_in[11];
    const float* bo2 = (const float*)d_in[12];
    float* out = (float*)d_out;

    cudaFuncSetAttribute(mm_gemm, cudaFuncAttributeMaxDynamicSharedMemorySize, DSM);

    __half *p,*wt,*wc,*q,*k,*v,*vt,*at,*wv,*tb;
    float *bc;
    cudaGetSymbolAddress((void**)&p,  g_p);
    cudaGetSymbolAddress((void**)&wt, g_wt);
    cudaGetSymbolAddress((void**)&wc, g_wc);
    cudaGetSymbolAddress((void**)&bc, g_bc);
    cudaGetSymbolAddress((void**)&q,  g_q);
    cudaGetSymbolAddress((void**)&k,  g_k);
    cudaGetSymbolAddress((void**)&v,  g_v);
    cudaGetSymbolAddress((void**)&vt, g_vt);
    cudaGetSymbolAddress((void**)&at, g_at);
    cudaGetSymbolAddress((void**)&wv, g_wv);
    cudaGetSymbolAddress((void**)&tb, g_t);

    __half* w1h  = wt + 0*DDn*DDn;   // W1 row-major fp16
    __half* wtq  = wt + 1*DDn*DDn;   // Wq^T
    __half* wtk  = wt + 2*DDn*DDn;   // Wk^T
    __half* wtv  = wt + 3*DDn*DDn;   // Wv^T
    __half* wto1 = wt + 4*DDn*DDn;
    __half* wto2 = wt + 5*DDn*DDn;
    __half* wcq = wc + 0*DDn*DDn;    // (W1 Wq)^T
    __half* wck = wc + 1*DDn*DDn;
    __half* wcv = wc + 2*DDn*DDn;
    float* bcq = bc + 0*DDn;
    float* bck = bc + 1*DDn;
    float* bcv = bc + 2*DDn;

    // 1. patchify
    {
        long long total = (long long)ROWS * DDn;
        patchify_h<<<(unsigned)((total + 255)/256), 256>>>(x, p);
    }
    // 2. weight prep
    {
        int nthr = DDn*DDn, blocks = (nthr + 255)/256;
        wconv_h <<<blocks,256>>>(W1,  w1h);
        wtrans_h<<<blocks,256>>>(Wq,  wtq);
        wtrans_h<<<blocks,256>>>(Wk,  wtk);
        wtrans_h<<<blocks,256>>>(Wv,  wtv);
        wtrans_h<<<blocks,256>>>(Wo1, wto1);
        wtrans_h<<<blocks,256>>>(Wo2, wto2);
        bias_comp<<<3,256>>>(b1, Wq, bq, bcq);
        bias_comp<<<3,256>>>(b1, Wk, bk, bck);
        bias_comp<<<3,256>>>(b1, Wv, bv, bcv);
    }
    // 3. composite weights: (W1 Wx)^T = mm(A=Wx^T, B=W1_rowmajor)
    gemm(wtq, w1h, nullptr, nullptr, wcq, nullptr,
         DDn, DDn, DDn, DDn, DDn, DDn, 0,0,0, 1,1, 1.f, 0, 0);
    gemm(wtk, w1h, nullptr, nullptr, wck, nullptr,
         DDn, DDn, DDn, DDn, DDn, DDn, 0,0,0, 1,1, 1.f, 0, 0);
    gemm(wtv, w1h, nullptr, nullptr, wcv, nullptr,
         DDn, DDn, DDn, DDn, DDn, DDn, 0,0,0, 1,1, 1.f, 0, 0);
    // 4. Q = p0 @ Wcq + bcq (remap picture-0 rows of p)
    gemm(p, wcq, bcq, nullptr, q, nullptr,
         QROWS, DDn, DDn, DDn, DDn, DDn, 0,0,0, 1,1, 1.f, 0, 1);
    // 5. K = p @ Wck + bck
    gemm(p, wck, bck, nullptr, k, nullptr,
         ROWS, DDn, DDn, DDn, DDn, DDn, 0,0,0, 1,1, 1.f, 0, 0);
    // 6. V = p @ Wcv + bcv
    gemm(p, wcv, bcv, nullptr, v, nullptr,
         ROWS, DDn, DDn, DDn, DDn, DDn, 0,0,0, 1,1, 1.f, 0, 0);
    // 7. V transpose -> Vt [z][768][256]
    {
        dim3 g(DDn/32, KPAD/32, NBat), b(32, 8);
        vtrans_h<<<g, b>>>(v, vt);
    }
    // 8. attn = softmax(scale * Q @ K^T)  (fused epilogue, batched)
    {
        float scale = 1.f / sqrtf((float)DDn);
        gemm(q, k, nullptr, nullptr, nullptr, at,
             SSn, SSn, DDn, DDn, DDn, KPAD,
             (long long)SSn*DDn, (long long)SSn*DDn, (long long)SSn*KPAD,
             NPIC, NBat, scale, 0, 0);
    }
    // 9. wv = attn @ V (B = Vt)
    gemm(at, vt, nullptr, nullptr, wv, nullptr,
         SSn, DDn, KPAD, KPAD, KPAD, DDn,
         (long long)SSn*KPAD, (long long)DDn*KPAD, (long long)SSn*DDn,
         1, NBat, 1.f, 0, 0);
    // 10. t = relu(wv @ Wo1 + bo1)
    gemm(wv, wto1, bo1, nullptr, tb, nullptr,
         ROWS, DDn, DDn, DDn, DDn, DDn, 0,0,0, 1,1, 1.f, 1, 0);
    // 11. out = t @ Wo2 + bo2
    gemm(tb, wto2, bo2, out, nullptr, nullptr,
         ROWS, DDn, DDn, DDn, DDn, DDn, 0,0,0, 1,1, 1.f, 0, 0);
}

// round 11
// speedup vs baseline: 1.0720x; 1.0720x over previous
#include <cuda_runtime.h>
#include <cuda_fp16.h>
#include <stdint.h>
#include <math.h>

// ================= problem constants =================
#define Bsz   32
#define NPIC  4
#define CCH   3
#define Him   224
#define Wim   224
#define PPs   16
#define HPn   14
#define SSn   196
#define DDn   768
#define ROWS  (Bsz*NPIC*SSn)   // 25088
#define QROWS (Bsz*SSn)        // 6272
#define NBat  (Bsz*NPIC)       // 128
#define KPAD  256
#define KVLD  1536             // fused K|V row stride

// ================= device scratch =================
__device__ __align__(1024) __half g_p  [ROWS*DDn];
__device__ __align__(1024) __half g_wt [6*DDn*DDn];   // 0=W1 rowmajor,1=WqT,2=WkT,3=WvT,4=Wo1T,5=Wo2T
__device__ __align__(1024) __half g_wc [3*DDn*DDn];   // composite (W1Wq)T,(W1Wk)T,(W1Wv)T
__device__ __align__(1024) float  g_bc [3*DDn];       // composite biases q,k,v
__device__ __align__(1024) __half g_q  [QROWS*DDn];
__device__ __align__(1024) __half g_kv [ROWS*KVLD];   // K cols 0..767, V cols 768..1535
__device__ __align__(1024) __half g_vt [NBat*DDn*KPAD];
__device__ __align__(1024) __half g_at [NBat*SSn*KPAD];
__device__ __align__(1024) __half g_wv [ROWS*DDn];
__device__ __align__(1024) __half g_t  [ROWS*DDn];

// ================= helpers =================
__device__ __forceinline__ uint32_t smem_u32(const void* p){
    uint32_t a;
    asm("{ .reg .u64 t; cvta.to.shared.u64 t, %1; cvt.u32.u64 %0, t; }" : "=r"(a) : "l"(p));
    return a;
}
#define SWZ128(o) ((o) ^ (((o) >> 3) & 0x70))

__device__ __forceinline__ void cp16(uint32_t dst, const void* src, int nbytes){
    asm volatile("cp.async.cg.shared.global [%0], [%1], 16, %2;"
                 :: "r"(dst), "l"(src), "r"(nbytes) : "memory");
}
__device__ __forceinline__ void cp_commit(){ asm volatile("cp.async.commit_group;" ::: "memory"); }
__device__ __forceinline__ void cp_wait2(){  asm volatile("cp.async.wait_group 2;" ::: "memory"); }

__device__ __forceinline__ void ldsm4(uint32_t& r0,uint32_t& r1,uint32_t& r2,uint32_t& r3,uint32_t a){
    asm volatile("ldmatrix.sync.aligned.m8n8.x4.shared.b16 {%0,%1,%2,%3}, [%4];"
        : "=r"(r0),"=r"(r1),"=r"(r2),"=r"(r3) : "r"(a));
}
__device__ __forceinline__ void mma16816(float* c, const uint32_t* a, const uint32_t* b){
    asm volatile("mma.sync.aligned.m16n8k16.row.col.f32.f16.f16.f32 "
        "{%0,%1,%2,%3}, {%4,%5,%6,%7}, {%8,%9}, {%0,%1,%2,%3};"
        : "+f"(c[0]),"+f"(c[1]),"+f"(c[2]),"+f"(c[3])
        : "r"(a[0]),"r"(a[1]),"r"(a[2]),"r"(a[3]), "r"(b[0]),"r"(b[1]));
}

// ================= patchify -> fp16 =================
__global__ void patchify_h(const float* __restrict__ x, __half* __restrict__ p)
{
    long long idx = (long long)blockIdx.x * blockDim.x + threadIdx.x;
    long long total = (long long)ROWS * DDn;
    if (idx >= total) return;
    int d    = (int)(idx % DDn);
    int rest = (int)(idx / DDn);
    int s    = rest % SSn;
    int pic  = rest / SSn;
    int c  = d >> 8;
    int rm = d & 255;
    int ph = rm >> 4;
    int pw = rm & 15;
    int i = s / HPn, j = s % HPn;
    long long src = (((long long)pic * CCH + c) * Him + (i*PPs + ph)) * Wim + (j*PPs + pw);
    p[idx] = __float2half(x[src]);
}

// ================= combined weight prep (1 launch) ==========
// slot 0: W1 row-major convert; slots 1-5: transpose of Wq,Wk,Wv,Wo1,Wo2
__global__ void wprep_all(const float* __restrict__ W1, const float* __restrict__ Wq,
                          const float* __restrict__ Wk, const float* __restrict__ Wv,
                          const float* __restrict__ Wo1, const float* __restrict__ Wo2,
                          __half* __restrict__ wt)
{
    int idx = blockIdx.x * blockDim.x + threadIdx.x;
    if (idx >= 6*DDn*DDn) return;
    int slot = idx / (DDn*DDn);
    int r    = idx % (DDn*DDn);
    if (slot == 0) { wt[idx] = __float2half(W1[r]); return; }
    int n = r / DDn, k = r % DDn;
    const float* W = (slot == 1) ? Wq : (slot == 2) ? Wk : (slot == 3) ? Wv
                   : (slot == 4) ? Wo1 : Wo2;
    wt[idx] = __float2half(W[k*DDn + n]);
}

// ================= combined composite bias (1 launch) ======
__global__ void bias_comp3(const float* __restrict__ b1,
                           const float* __restrict__ Wq, const float* __restrict__ bq,
                           const float* __restrict__ Wk, const float* __restrict__ bk,
                           const float* __restrict__ Wv, const float* __restrict__ bv,
                           float* __restrict__ bc)
{
    int idx = blockIdx.x * blockDim.x + threadIdx.x;
    if (idx >= 3*DDn) return;
    int which = idx / DDn, n = idx % DDn;
    const float* W  = (which == 0) ? Wq : (which == 1) ? Wk : Wv;
    const float* bx = (which == 0) ? bq : (which == 1) ? bk : bv;
    float s = bx[n];
    for (int k = 0; k < DDn; k++) s += b1[k] * W[k*DDn + n];
    bc[idx] = s;
}

// ================= V transpose from fused KV (pad 256) =====
__global__ void vtrans_h(const __half* __restrict__ KV, __half* __restrict__ vt)
{
    __shared__ __half tile[32][33];
    int z  = blockIdx.z;
    int d0 = blockIdx.x * 32;
    int s0 = blockIdx.y * 32;
    int tx = threadIdx.x, ty = threadIdx.y;
    for (int sy = ty; sy < 32; sy += 8) {
        int s = s0 + sy, d = d0 + tx;
        tile[sy][tx] = (s < SSn) ? KV[((long long)z*SSn + s)*KVLD + DDn + d]
                                 : __float2half(0.f);
    }
    __syncthreads();
    for (int dy = ty; dy < 32; dy += 8) {
        int d = d0 + dy, s = s0 + tx;
        vt[((long long)z*DDn + d)*KPAD + s] = tile[tx][dy];
    }
}

// ================= mma.sync fp16 GEMM (128x256 tile, 3-stage pipeline) =====
#define BMt 128
#define BNt 256
#define BKt 64
#define NTHR 256
#define TILEA 16384
#define TILEB 32768
#define STGSZ (TILEA + TILEB)
#define DSM   (3*STGSZ + 1024)

__global__ void __launch_bounds__(NTHR)
mm_gemm(const __half* __restrict__ A, const __half* __restrict__ B,
        const float* __restrict__ bias,
        float* __restrict__ Cf, __half* __restrict__ Ch, __half* __restrict__ Smx,
        int M, int Nvalid, int K, int ldA, int ldB, int ldC,
        long long sA, long long sB, long long sC, int zdivA,
        float alpha, int relu, int remapA)
{
    extern __shared__ char dsm[];
    uint32_t dyn  = smem_u32(dsm);
    uint32_t base = (dyn + 1023u) & ~1023u;
    const uint32_t stg[3] = { base, base + STGSZ, base + 2*STGSZ };

    const int t = threadIdx.x, lane = t & 31, w = t >> 5;
    const int wm = w & 1, wn = w >> 1;
    const int z = blockIdx.z;
    const int m0 = blockIdx.y * BMt;
    const int n0 = blockIdx.x * BNt;

    const __half* Az = A + (long long)(z / zdivA) * sA;
    const __half* Bz = B + (long long)z * sB;
    float* Cfz = Cf ? Cf + (long long)z * sC : nullptr;
    __half* Chz = Ch ? Ch + (long long)z * sC : nullptr;
    __half* Smxz = Smx ? Smx + (long long)z * sC : nullptr;

    float acc[4][8][4];
#pragma unroll
    for (int a = 0; a < 4; a++)
#pragma unroll
        for (int b = 0; b < 8; b++)
#pragma unroll
            for (int c = 0; c < 4; c++) acc[a][b][c] = 0.f;

    const int ITERS = K / BKt;

#define LOAD_STAGE(ITN, BUF)                                                         \
    {                                                                                \
        int k0 = (ITN) * BKt;                                                        \
        _Pragma("unroll")                                                            \
        for (int j = 0; j < 4; j++) {                                                \
            int flat = t + j*256;                                                    \
            int row = flat >> 3, cc = flat & 7;                                      \
            uint32_t so = SWZ128((uint32_t)(row*128 + cc*16));                       \
            int gr = m0 + row;                                                       \
            int ok = gr < M;                                                         \
            long long pr = 0;                                                        \
            if (ok) pr = remapA ? (long long)gr + (gr/SSn)*(NPIC*SSn - SSn)          \
                                : (long long)gr;                                     \
            cp16(stg[BUF] + so, Az + pr*ldA + k0 + cc*8, ok ? 16 : 0);               \
        }                                                                            \
        _Pragma("unroll")                                                            \
        for (int j = 0; j < 8; j++) {                                                \
            int flat = t + j*256;                                                    \
            int row = flat >> 3, cc = flat & 7;                                      \
            uint32_t so = SWZ128((uint32_t)(row*128 + cc*16));                       \
            int gn = n0 + row;                                                       \
            int okb = gn < Nvalid;                                                   \
            long long pn = okb ? gn : 0;                                             \
            cp16(stg[BUF] + TILEA + so, Bz + pn*ldB + k0 + cc*8, okb ? 16 : 0);      \
        }                                                                            \
    }

    LOAD_STAGE(0, 0); cp_commit();
    LOAD_STAGE(1, 1); cp_commit();

    const int rl = lane & 15, hh = lane >> 4;

    for (int itn = 0; itn < ITERS; itn++) {
        int buf = itn % 3;
        if (itn + 2 < ITERS) { int nb = (itn + 2) % 3; LOAD_STAGE(itn + 2, nb); }
        cp_commit();
        cp_wait2();
        __syncthreads();

        uint32_t sA_ = stg[buf], sB_ = stg[buf] + TILEA;
#pragma unroll
        for (int ks = 0; ks < 4; ks++) {
            int c = ks*2 + hh;
            uint32_t af[4][4], bf[8][2];
#pragma unroll
            for (int mt = 0; mt < 4; mt++) {
                int row = wm*64 + mt*16 + rl;
                uint32_t so = SWZ128((uint32_t)(row*128 + c*16));
                ldsm4(af[mt][0], af[mt][1], af[mt][2], af[mt][3], sA_ + so);
            }
#pragma unroll
            for (int bt = 0; bt < 4; bt++) {
                int row = wn*64 + bt*16 + rl;
                uint32_t so = SWZ128((uint32_t)(row*128 + c*16));
                uint32_t r0, r1, r2, r3;
                ldsm4(r0, r1, r2, r3, sB_ + so);
                bf[bt*2][0]   = r0;  bf[bt*2][1]   = r2;
                bf[bt*2+1][0] = r1;  bf[bt*2+1][1] = r3;
            }
#pragma unroll
            for (int mt = 0; mt < 4; mt++)
#pragma unroll
                for (int nt = 0; nt < 8; nt++)
                    mma16816(acc[mt][nt], af[mt], bf[nt]);
        }
    }

    const int r0l = lane >> 2, cl = (lane & 3) * 2;

    if (Smx) {
        // ---- fused softmax epilogue (CTA holds full rows) ----
        __half* stage = (__half*)(dsm + (base - dyn));
        __syncthreads();
#pragma unroll
        for (int mt = 0; mt < 4; mt++)
#pragma unroll
            for (int nt = 0; nt < 8; nt++) {
                int col = wn*64 + nt*8 + cl;
#pragma unroll
                for (int half = 0; half < 2; half++) {
                    int r = wm*64 + mt*16 + r0l + half*8;
                    stage[r*256 + col]     = __float2half(acc[mt][nt][half*2 + 0] * alpha);
                    stage[r*256 + col + 1] = __float2half(acc[mt][nt][half*2 + 1] * alpha);
                }
            }
        __syncthreads();
        for (int rr = 0; rr < 16; rr++) {
            int r = w*16 + rr;
            int gr = m0 + r;
            if (gr >= M) continue;
            float v[7];
            float mx = -INFINITY;
#pragma unroll
            for (int i = 0; i < 7; i++) {
                int c = lane + i*32;
                v[i] = (c < SSn) ? __half2float(stage[r*256 + c]) : -INFINITY;
                mx = fmaxf(mx, v[i]);
            }
#pragma unroll
            for (int o = 16; o > 0; o >>= 1) mx = fmaxf(mx, __shfl_xor_sync(0xffffffffu, mx, o));
            float sum = 0.f;
#pragma unroll
            for (int i = 0; i < 7; i++) {
                int c = lane + i*32;
                if (c < SSn) { v[i] = __expf(v[i] - mx); sum += v[i]; } else v[i] = 0.f;
            }
#pragma unroll
            for (int o = 16; o > 0; o >>= 1) sum += __shfl_xor_sync(0xffffffffu, sum, o);
            float inv = 1.f / sum;
            __half* orow = Smxz + (long long)gr * KPAD;
#pragma unroll
            for (int i = 0; i < 8; i++) {
                int c = lane + i*32;
                float val = (i < 7 && c < SSn) ? v[i] * inv : 0.f;
                orow[c] = __float2half(val);
            }
        }
        return;
    }

    // ---- normal epilogue ----
#pragma unroll
    for (int mt = 0; mt < 4; mt++) {
#pragma unroll
        for (int nt = 0; nt < 8; nt++) {
            int gc = n0 + wn*64 + nt*8 + cl;
#pragma unroll
            for (int half = 0; half < 2; half++) {
                int gr = m0 + wm*64 + mt*16 + r0l + half*8;
                if (gr >= M) continue;
                float v0 = acc[mt][nt][half*2 + 0] * alpha;
                float v1 = acc[mt][nt][half*2 + 1] * alpha;
                if (bias) { v0 += __ldg(bias + gc); v1 += __ldg(bias + gc + 1); }
                if (relu) { v0 = fmaxf(v0, 0.f); v1 = fmaxf(v1, 0.f); }
                long long o = (long long)gr * ldC + gc;
                if (gc < Nvalid) {
                    if (Cfz) Cfz[o] = v0;
                    if (Chz) Chz[o] = __float2half(v0);
                }
                if (gc + 1 < Nvalid) {
                    if (Cfz) Cfz[o+1] = v1;
                    if (Chz) Chz[o+1] = __float2half(v1);
                }
            }
        }
    }
}

// ================= host side =================
static void gemm(const __half* A, const __half* B, const float* bias,
                 float* Cf, __half* Ch, __half* Smx,
                 int M, int Nvalid, int K, int ldA, int ldB, int ldC,
                 long long sA, long long sB, long long sC, int zdivA, int nz,
                 float alpha, int relu, int remapA)
{
    dim3 g((Nvalid + BNt - 1)/BNt, (M + BMt - 1)/BMt, nz);
    mm_gemm<<<g, NTHR, DSM>>>(A, B, bias, Cf, Ch, Smx,
                              M, Nvalid, K, ldA, ldB, ldC, sA, sB, sC,
                              zdivA, alpha, relu, remapA);
}

extern "C" void kernel_launch(void* const* d_in, const int* in_sizes, int n_in,
                              void* d_out, int out_size)
{
    const float* x   = (const float*)d_in[0];
    const float* W1  = (const float*)d_in[1];
    const float* b1  = (const float*)d_in[2];
    const float* Wq  = (const float*)d_in[3];
    const float* bq  = (const float*)d_in[4];
    const float* Wk  = (const float*)d_in[5];
    const float* bk  = (const float*)d_in[6];
    const float* Wv  = (const float*)d_in[7];
    const float* bv  = (const float*)d_in[8];
    const float* Wo1 = (const float*)d_in[9];
    const float* bo1 = (const float*)d_in[10];
    const float* Wo2 = (const float*)d_in[11];
    const float* bo2 = (const float*)d_in[12];
    float* out = (float*)d_out;

    cudaFuncSetAttribute(mm_gemm, cudaFuncAttributeMaxDynamicSharedMemorySize, DSM);

    __half *p,*wt,*wc,*q,*kv,*vt,*at,*wv,*tb;
    float *bc;
    cudaGetSymbolAddress((void**)&p,  g_p);
    cudaGetSymbolAddress((void**)&wt, g_wt);
    cudaGetSymbolAddress((void**)&wc, g_wc);
    cudaGetSymbolAddress((void**)&bc, g_bc);
    cudaGetSymbolAddress((void**)&q,  g_q);
    cudaGetSymbolAddress((void**)&kv, g_kv);
    cudaGetSymbolAddress((void**)&vt, g_vt);
    cudaGetSymbolAddress((void**)&at, g_at);
    cudaGetSymbolAddress((void**)&wv, g_wv);
    cudaGetSymbolAddress((void**)&tb, g_t);

    __half* w1h  = wt + 0*DDn*DDn;   // W1 row-major fp16
    __half* wtqkv = wt + 1*DDn*DDn;  // [WqT;WkT;WvT] stacked (2304 x 768)
    __half* wto1 = wt + 4*DDn*DDn;
    __half* wto2 = wt + 5*DDn*DDn;
    __half* wcq  = wc + 0*DDn*DDn;   // (W1 Wq)^T
    __half* wckv = wc + 1*DDn*DDn;   // [(W1Wk)T;(W1Wv)T] stacked (1536 x 768)
    float* bcq  = bc + 0*DDn;
    float* bckv = bc + 1*DDn;        // 1536 entries (k then v)

    // 1. patchify
    {
        long long total = (long long)ROWS * DDn;
        patchify_h<<<(unsigned)((total + 255)/256), 256>>>(x, p);
    }
    // 2. weight prep (single launch) + composite biases (single launch)
    wprep_all<<<(6*DDn*DDn + 255)/256, 256>>>(W1, Wq, Wk, Wv, Wo1, Wo2, wt);
    bias_comp3<<<(3*DDn + 255)/256, 256>>>(b1, Wq, bq, Wk, bk, Wv, bv, bc);
    // 3. composite weights, ONE launch: C[2304][768] = [WqT;WkT;WvT] @ W1^T
    gemm(wtqkv, w1h, nullptr, nullptr, wc, nullptr,
         3*DDn, DDn, DDn, DDn, DDn, DDn, 0,0,0, 1,1, 1.f, 0, 0);
    // 4. Q = p0 @ Wcq + bcq (remap picture-0 rows of p)
    gemm(p, wcq, bcq, nullptr, q, nullptr,
         QROWS, DDn, DDn, DDn, DDn, DDn, 0,0,0, 1,1, 1.f, 0, 1);
    // 5. K|V = p @ [Wck|Wcv] + [bck|bcv]  (fused, N=1536)
    gemm(p, wckv, bckv, nullptr, kv, nullptr,
         ROWS, KVLD, DDn, DDn, DDn, KVLD, 0,0,0, 1,1, 1.f, 0, 0);
    // 6. V transpose -> Vt [z][768][256]
    {
        dim3 g(DDn/32, KPAD/32, NBat), b(32, 8);
        vtrans_h<<<g, b>>>(kv, vt);
    }
    // 7. attn = softmax(scale * Q @ K^T)  (fused epilogue, batched; K rows stride 1536)
    {
        float scale = 1.f / sqrtf((float)DDn);
        gemm(q, kv, nullptr, nullptr, nullptr, at,
             SSn, SSn, DDn, DDn, KVLD, KPAD,
             (long long)SSn*DDn, (long long)SSn*KVLD, (long long)SSn*KPAD,
             NPIC, NBat, scale, 0, 0);
    }
    // 8. wv = attn @ V (B = Vt)
    gemm(at, vt, nullptr, nullptr, wv, nullptr,
         SSn, DDn, KPAD, KPAD, KPAD, DDn,
         (long long)SSn*KPAD, (long long)DDn*KPAD, (long long)SSn*DDn,
         1, NBat, 1.f, 0, 0);
    // 9. t = relu(wv @ Wo1 + bo1)
    gemm(wv, wto1, bo1, nullptr, tb, nullptr,
         ROWS, DDn, DDn, DDn, DDn, DDn, 0,0,0, 1,1, 1.f, 1, 0);
    // 10. out = t @ Wo2 + bo2
    gemm(tb, wto2, bo2, out, nullptr, nullptr,
         ROWS, DDn, DDn, DDn, DDn, DDn, 0,0,0, 1,1, 1.f, 0, 0);
}

// round 14
// speedup vs baseline: 1.1310x; 1.0551x over previous
#include <cuda_runtime.h>
#include <cuda_fp16.h>
#include <stdint.h>
#include <math.h>

// ================= problem constants =================
#define Bsz   32
#define NPIC  4
#define CCH   3
#define Him   224
#define Wim   224
#define PPs   16
#define HPn   14
#define SSn   196
#define DDn   768
#define ROWS  (Bsz*NPIC*SSn)   // 25088
#define QROWS (Bsz*SSn)        // 6272
#define NBat  (Bsz*NPIC)       // 128
#define KPAD  256
#define KVLD  1536             // fused K|V row stride

// ================= device scratch =================
__device__ __align__(1024) __half g_p  [ROWS*DDn];
__device__ __align__(1024) __half g_wt [6*DDn*DDn];   // 0=W1 rowmajor,1-5=transposed Wq,Wk,Wv,Wo1,Wo2
__device__ __align__(1024) __half g_wc [3*DDn*DDn];   // composite (W1Wq)T,(W1Wk)T,(W1Wv)T
__device__ __align__(1024) float  g_bc [3*DDn];       // composite biases q,k,v
__device__ __align__(1024) __half g_q  [QROWS*DDn];
__device__ __align__(1024) __half g_kv [ROWS*KVLD];   // K cols 0..767, V cols 768..1535
__device__ __align__(1024) __half g_vt [NBat*DDn*KPAD];
__device__ __align__(1024) __half g_at [NBat*SSn*KPAD];
__device__ __align__(1024) __half g_wv [ROWS*DDn];
__device__ __align__(1024) __half g_t  [ROWS*DDn];

// ================= helpers =================
__device__ __forceinline__ uint32_t smem_u32(const void* p){
    uint32_t a;
    asm("{ .reg .u64 t; cvta.to.shared.u64 t, %1; cvt.u32.u64 %0, t; }" : "=r"(a) : "l"(p));
    return a;
}
#define SWZ128(o) ((o) ^ (((o) >> 3) & 0x70))

__device__ __forceinline__ void cp16(uint32_t dst, const void* src, int nbytes){
    asm volatile("cp.async.cg.shared.global [%0], [%1], 16, %2;"
                 :: "r"(dst), "l"(src), "r"(nbytes) : "memory");
}
__device__ __forceinline__ void cp_commit(){ asm volatile("cp.async.commit_group;" ::: "memory"); }
__device__ __forceinline__ void cp_wait3(){  asm volatile("cp.async.wait_group 3;" ::: "memory"); }

__device__ __forceinline__ void ldsm4(uint32_t& r0,uint32_t& r1,uint32_t& r2,uint32_t& r3,uint32_t a){
    asm volatile("ldmatrix.sync.aligned.m8n8.x4.shared.b16 {%0,%1,%2,%3}, [%4];"
        : "=r"(r0),"=r"(r1),"=r"(r2),"=r"(r3) : "r"(a));
}
__device__ __forceinline__ void mma16816(float* c, const uint32_t* a, const uint32_t* b){
    asm volatile("mma.sync.aligned.m16n8k16.row.col.f32.f16.f16.f32 "
        "{%0,%1,%2,%3}, {%4,%5,%6,%7}, {%8,%9}, {%0,%1,%2,%3};"
        : "+f"(c[0]),"+f"(c[1]),"+f"(c[2]),"+f"(c[3])
        : "r"(a[0]),"r"(a[1]),"r"(a[2]),"r"(a[3]), "r"(b[0]),"r"(b[1]));
}

// ========== fused prep: patchify + weight convert/transpose + composite bias ==========
#define PATCH_BLK ((ROWS*DDn)/256)          // 75264
#define WPREP_BLK ((6*DDn*DDn)/256)         // 13824
#define BIAS_BLK  9
__global__ void prep_all(const float* __restrict__ x,
                         const float* __restrict__ W1, const float* __restrict__ Wq,
                         const float* __restrict__ Wk, const float* __restrict__ Wv,
                         const float* __restrict__ Wo1, const float* __restrict__ Wo2,
                         const float* __restrict__ b1, const float* __restrict__ bq,
                         const float* __restrict__ bk, const float* __restrict__ bv,
                         __half* __restrict__ p, __half* __restrict__ wt,
                         float* __restrict__ bc)
{
    int b = blockIdx.x;
    int t = threadIdx.x;
    if (b < PATCH_BLK) {
        long long idx = (long long)b * 256 + t;
        int d    = (int)(idx % DDn);
        int rest = (int)(idx / DDn);
        int s    = rest % SSn;
        int pic  = rest / SSn;
        int c  = d >> 8;
        int rm = d & 255;
        int ph = rm >> 4;
        int pw = rm & 15;
        int i = s / HPn, j = s % HPn;
        long long src = (((long long)pic * CCH + c) * Him + (i*PPs + ph)) * Wim + (j*PPs + pw);
        p[idx] = __float2half(x[src]);
        return;
    }
    b -= PATCH_BLK;
    if (b < WPREP_BLK) {
        int idx = b * 256 + t;
        int slot = idx / (DDn*DDn);
        int r    = idx % (DDn*DDn);
        if (slot == 0) { wt[idx] = __float2half(W1[r]); return; }
        int n = r / DDn, k = r % DDn;
        const float* W = (slot == 1) ? Wq : (slot == 2) ? Wk : (slot == 3) ? Wv
                       : (slot == 4) ? Wo1 : Wo2;
        wt[idx] = __float2half(W[k*DDn + n]);
        return;
    }
    b -= WPREP_BLK;
    {
        int idx = b * 256 + t;
        if (idx >= 3*DDn) return;
        int which = idx / DDn, n = idx % DDn;
        const float* W  = (which == 0) ? Wq : (which == 1) ? Wk : Wv;
        const float* bx = (which == 0) ? bq : (which == 1) ? bk : bv;
        float s = bx[n];
        for (int k = 0; k < DDn; k++) s += b1[k] * W[k*DDn + n];
        bc[idx] = s;
    }
}

// ================= V transpose from fused KV (pad 256) =====
__global__ void vtrans_h(const __half* __restrict__ KV, __half* __restrict__ vt)
{
    __shared__ __half tile[32][33];
    int z  = blockIdx.z;
    int d0 = blockIdx.x * 32;
    int s0 = blockIdx.y * 32;
    int tx = threadIdx.x, ty = threadIdx.y;
    for (int sy = ty; sy < 32; sy += 8) {
        int s = s0 + sy, d = d0 + tx;
        tile[sy][tx] = (s < SSn) ? KV[((long long)z*SSn + s)*KVLD + DDn + d]
                                 : __float2half(0.f);
    }
    __syncthreads();
    for (int dy = ty; dy < 32; dy += 8) {
        int d = d0 + dy, s = s0 + tx;
        vt[((long long)z*DDn + d)*KPAD + s] = tile[tx][dy];
    }
}

// ================= mma.sync fp16 GEMM (128x256 tile, 4-stage pipeline) =====
#define BMt 128
#define BNt 256
#define BKt 64
#define NTHR 256
#define TILEA 16384
#define TILEB 32768
#define STGSZ (TILEA + TILEB)
#define NSTG  4
#define DSM   (NSTG*STGSZ + 1024)

__global__ void __launch_bounds__(NTHR)
mm_gemm(const __half* __restrict__ A, const __half* __restrict__ B,
        const float* __restrict__ bias,
        float* __restrict__ Cf, __half* __restrict__ Ch, __half* __restrict__ Smx,
        int M, int Nvalid, int K, int ldA, int ldB, int ldC,
        long long sA, long long sB, long long sC, int zdivA,
        float alpha, int relu, int remapA)
{
    extern __shared__ char dsm[];
    uint32_t dyn  = smem_u32(dsm);
    uint32_t base = (dyn + 1023u) & ~1023u;
    const uint32_t stg[NSTG] = { base, base + STGSZ, base + 2*STGSZ, base + 3*STGSZ };

    const int t = threadIdx.x, lane = t & 31, w = t >> 5;
    const int wm = w & 1, wn = w >> 1;          // 2 x 4 warps; warp tile 64x64
    const int z = blockIdx.z;
    const int m0 = blockIdx.y * BMt;
    const int n0 = blockIdx.x * BNt;

    const __half* Az = A + (long long)(z / zdivA) * sA;
    const __half* Bz = B + (long long)z * sB;
    float* Cfz = Cf ? Cf + (long long)z * sC : nullptr;
    __half* Chz = Ch ? Ch + (long long)z * sC : nullptr;
    __half* Smxz = Smx ? Smx + (long long)z * sC : nullptr;

    float acc[4][8][4];
#pragma unroll
    for (int a = 0; a < 4; a++)
#pragma unroll
        for (int b = 0; b < 8; b++)
#pragma unroll
            for (int c = 0; c < 4; c++) acc[a][b][c] = 0.f;

    const int ITERS = K / BKt;   // >= 4 for every call in this pipeline

#define LOAD_STAGE(ITN, BUF)                                                         \
    {                                                                                \
        int k0 = (ITN) * BKt;                                                        \
        _Pragma("unroll")                                                            \
        for (int j = 0; j < 4; j++) {                                                \
            int flat = t + j*256;                                                    \
            int row = flat >> 3, cc = flat & 7;                                      \
            uint32_t so = SWZ128((uint32_t)(row*128 + cc*16));                       \
            int gr = m0 + row;                                                       \
            int ok = gr < M;                                                         \
            long long pr = 0;                                                        \
            if (ok) pr = remapA ? (long long)gr + (gr/SSn)*(NPIC*SSn - SSn)          \
                                : (long long)gr;                                     \
            cp16(stg[BUF] + so, Az + pr*ldA + k0 + cc*8, ok ? 16 : 0);               \
        }                                                                            \
        _Pragma("unroll")                                                            \
        for (int j = 0; j < 8; j++) {                                                \
            int flat = t + j*256;                                                    \
            int row = flat >> 3, cc = flat & 7;                                      \
            uint32_t so = SWZ128((uint32_t)(row*128 + cc*16));                       \
            int gn = n0 + row;                                                       \
            int okb = gn < Nvalid;                                                   \
            long long pn = okb ? gn : 0;                                             \
            cp16(stg[BUF] + TILEA + so, Bz + pn*ldB + k0 + cc*8, okb ? 16 : 0);      \
        }                                                                            \
    }

    LOAD_STAGE(0, 0); cp_commit();
    LOAD_STAGE(1, 1); cp_commit();
    LOAD_STAGE(2, 2); cp_commit();

    const int rl = lane & 15, hh = lane >> 4;

    for (int itn = 0; itn < ITERS; itn++) {
        int buf = itn & 3;
        if (itn + 3 < ITERS) { int nb = (itn + 3) & 3; LOAD_STAGE(itn + 3, nb); }
        cp_commit();
        cp_wait3();
        __syncthreads();

        uint32_t sA_ = stg[buf], sB_ = stg[buf] + TILEA;
#pragma unroll
        for (int ks = 0; ks < 4; ks++) {
            int c = ks*2 + hh;
            uint32_t af[4][4], bf[8][2];
#pragma unroll
            for (int mt = 0; mt < 4; mt++) {
                int row = wm*64 + mt*16 + rl;
                uint32_t so = SWZ128((uint32_t)(row*128 + c*16));
                ldsm4(af[mt][0], af[mt][1], af[mt][2], af[mt][3], sA_ + so);
            }
#pragma unroll
            for (int bt = 0; bt < 4; bt++) {
                int row = wn*64 + bt*16 + rl;
                uint32_t so = SWZ128((uint32_t)(row*128 + c*16));
                uint32_t r0, r1, r2, r3;
                ldsm4(r0, r1, r2, r3, sB_ + so);
                bf[bt*2][0]   = r0;  bf[bt*2][1]   = r2;
                bf[bt*2+1][0] = r1;  bf[bt*2+1][1] = r3;
            }
#pragma unroll
            for (int mt = 0; mt < 4; mt++)
#pragma unroll
                for (int nt = 0; nt < 8; nt++)
                    mma16816(acc[mt][nt], af[mt], bf[nt]);
        }
    }

    const int r0l = lane >> 2, cl = (lane & 3) * 2;

    if (Smx) {
        // ---- fused softmax epilogue (CTA holds full rows) ----
        __half* stage = (__half*)(dsm + (base - dyn));
        __syncthreads();
#pragma unroll
        for (int mt = 0; mt < 4; mt++)
#pragma unroll
            for (int nt = 0; nt < 8; nt++) {
                int col = wn*64 + nt*8 + cl;
#pragma unroll
                for (int half = 0; half < 2; half++) {
                    int r = wm*64 + mt*16 + r0l + half*8;
                    stage[r*256 + col]     = __float2half(acc[mt][nt][half*2 + 0] * alpha);
                    stage[r*256 + col + 1] = __float2half(acc[mt][nt][half*2 + 1] * alpha);
                }
            }
        __syncthreads();
        for (int rr = 0; rr < 16; rr++) {
            int r = w*16 + rr;
            int gr = m0 + r;
            if (gr >= M) continue;
            float v[7];
            float mx = -INFINITY;
#pragma unroll
            for (int i = 0; i < 7; i++) {
                int c = lane + i*32;
                v[i] = (c < SSn) ? __half2float(stage[r*256 + c]) : -INFINITY;
                mx = fmaxf(mx, v[i]);
            }
#pragma unroll
            for (int o = 16; o > 0; o >>= 1) mx = fmaxf(mx, __shfl_xor_sync(0xffffffffu, mx, o));
            float sum = 0.f;
#pragma unroll
            for (int i = 0; i < 7; i++) {
                int c = lane + i*32;
                if (c < SSn) { v[i] = __expf(v[i] - mx); sum += v[i]; } else v[i] = 0.f;
            }
#pragma unroll
            for (int o = 16; o > 0; o >>= 1) sum += __shfl_xor_sync(0xffffffffu, sum, o);
            float inv = 1.f / sum;
            __half* orow = Smxz + (long long)gr * KPAD;
#pragma unroll
            for (int i = 0; i < 8; i++) {
                int c = lane + i*32;
                float val = (i < 7 && c < SSn) ? v[i] * inv : 0.f;
                orow[c] = __float2half(val);
            }
        }
        return;
    }

    // ---- normal epilogue ----
#pragma unroll
    for (int mt = 0; mt < 4; mt++) {
#pragma unroll
        for (int nt = 0; nt < 8; nt++) {
            int gc = n0 + wn*64 + nt*8 + cl;
#pragma unroll
            for (int half = 0; half < 2; half++) {
                int gr = m0 + wm*64 + mt*16 + r0l + half*8;
                if (gr >= M) continue;
                float v0 = acc[mt][nt][half*2 + 0] * alpha;
                float v1 = acc[mt][nt][half*2 + 1] * alpha;
                if (bias) { v0 += __ldg(bias + gc); v1 += __ldg(bias + gc + 1); }
                if (relu) { v0 = fmaxf(v0, 0.f); v1 = fmaxf(v1, 0.f); }
                long long o = (long long)gr * ldC + gc;
                if (gc < Nvalid) {
                    if (Cfz) Cfz[o] = v0;
                    if (Chz) Chz[o] = __float2half(v0);
                }
                if (gc + 1 < Nvalid) {
                    if (Cfz) Cfz[o+1] = v1;
                    if (Chz) Chz[o+1] = __float2half(v1);
                }
            }
        }
    }
}

// ================= host side =================
static void gemm(const __half* A, const __half* B, const float* bias,
                 float* Cf, __half* Ch, __half* Smx,
                 int M, int Nvalid, int K, int ldA, int ldB, int ldC,
                 long long sA, long long sB, long long sC, int zdivA, int nz,
                 float alpha, int relu, int remapA)
{
    dim3 g((Nvalid + BNt - 1)/BNt, (M + BMt - 1)/BMt, nz);
    mm_gemm<<<g, NTHR, DSM>>>(A, B, bias, Cf, Ch, Smx,
                              M, Nvalid, K, ldA, ldB, ldC, sA, sB, sC,
                              zdivA, alpha, relu, remapA);
}

extern "C" void kernel_launch(void* const* d_in, const int* in_sizes, int n_in,
                              void* d_out, int out_size)
{
    const float* x   = (const float*)d_in[0];
    const float* W1  = (const float*)d_in[1];
    const float* b1  = (const float*)d_in[2];
    const float* Wq  = (const float*)d_in[3];
    const float* bq  = (const float*)d_in[4];
    const float* Wk  = (const float*)d_in[5];
    const float* bk  = (const float*)d_in[6];
    const float* Wv  = (const float*)d_in[7];
    const float* bv  = (const float*)d_in[8];
    const float* Wo1 = (const float*)d_in[9];
    const float* bo1 = (const float*)d_in[10];
    const float* Wo2 = (const float*)d_in[11];
    const float* bo2 = (const float*)d_in[12];
    float* out = (float*)d_out;

    cudaFuncSetAttribute(mm_gemm, cudaFuncAttributeMaxDynamicSharedMemorySize, DSM);

    __half *p,*wt,*wc,*q,*kv,*vt,*at,*wv,*tb;
    float *bc;
    cudaGetSymbolAddress((void**)&p,  g_p);
    cudaGetSymbolAddress((void**)&wt, g_wt);
    cudaGetSymbolAddress((void**)&wc, g_wc);
    cudaGetSymbolAddress((void**)&bc, g_bc);
    cudaGetSymbolAddress((void**)&q,  g_q);
    cudaGetSymbolAddress((void**)&kv, g_kv);
    cudaGetSymbolAddress((void**)&vt, g_vt);
    cudaGetSymbolAddress((void**)&at, g_at);
    cudaGetSymbolAddress((void**)&wv, g_wv);
    cudaGetSymbolAddress((void**)&tb, g_t);

    __half* w1h   = wt + 0*DDn*DDn;   // W1 row-major fp16
    __half* wtqkv = wt + 1*DDn*DDn;   // [WqT;WkT;WvT] stacked (2304 x 768)
    __half* wto1  = wt + 4*DDn*DDn;
    __half* wto2  = wt + 5*DDn*DDn;
    __half* wcq   = wc + 0*DDn*DDn;   // (W1 Wq)^T
    __half* wckv  = wc + 1*DDn*DDn;   // [(W1Wk)T;(W1Wv)T] stacked (1536 x 768)
    float* bcq  = bc + 0*DDn;
    float* bckv = bc + 1*DDn;

    // 1. fused prep: patchify + weight convert/transpose + composite biases
    prep_all<<<PATCH_BLK + WPREP_BLK + BIAS_BLK, 256>>>(
        x, W1, Wq, Wk, Wv, Wo1, Wo2, b1, bq, bk, bv, p, wt, bc);
    // 2. composite weights, one launch: [2304][768] = [WqT;WkT;WvT] @ W1^T
    gemm(wtqkv, w1h, nullptr, nullptr, wc, nullptr,
         3*DDn, DDn, DDn, DDn, DDn, DDn, 0,0,0, 1,1, 1.f, 0, 0);
    // 3. Q = p0 @ Wcq + bcq (remap picture-0 rows of p)
    gemm(p, wcq, bcq, nullptr, q, nullptr,
         QROWS, DDn, DDn, DDn, DDn, DDn, 0,0,0, 1,1, 1.f, 0, 1);
    // 4. K|V = p @ [Wck|Wcv] + [bck|bcv]  (fused, N=1536)
    gemm(p, wckv, bckv, nullptr, kv, nullptr,
         ROWS, KVLD, DDn, DDn, DDn, KVLD, 0,0,0, 1,1, 1.f, 0, 0);
    // 5. V transpose -> Vt [z][768][256]
    {
        dim3 g(DDn/32, KPAD/32, NBat), b(32, 8);
        vtrans_h<<<g, b>>>(kv, vt);
    }
    // 6. attn = softmax(scale * Q @ K^T)  (fused epilogue, batched)
    {
        float scale = 1.f / sqrtf((float)DDn);
        gemm(q, kv, nullptr, nullptr, nullptr, at,
             SSn, SSn, DDn, DDn, KVLD, KPAD,
             (long long)SSn*DDn, (long long)SSn*KVLD, (long long)SSn*KPAD,
             NPIC, NBat, scale, 0, 0);
    }
    // 7. wv = attn @ V (B = Vt)
    gemm(at, vt, nullptr, nullptr, wv, nullptr,
         SSn, DDn, KPAD, KPAD, KPAD, DDn,
         (long long)SSn*KPAD, (long long)DDn*KPAD, (long long)SSn*DDn,
         1, NBat, 1.f, 0, 0);
    // 8. t = relu(wv @ Wo1 + bo1)
    gemm(wv, wto1, bo1, nullptr, tb, nullptr,
         ROWS, DDn, DDn, DDn, DDn, DDn, 0,0,0, 1,1, 1.f, 1, 0);
    // 9. out = t @ Wo2 + bo2
    gemm(tb, wto2, bo2, out, nullptr, nullptr,
         ROWS, DDn, DDn, DDn, DDn, DDn, 0,0,0, 1,1, 1.f, 0, 0);
}

// round 15
// speedup vs baseline: 1.1696x; 1.0341x over previous
#include <cuda_runtime.h>
#include <cuda_fp16.h>
#include <stdint.h>
#include <math.h>

// ================= problem constants =================
#define Bsz   32
#define NPIC  4
#define CCH   3
#define Him   224
#define Wim   224
#define PPs   16
#define HPn   14
#define SSn   196
#define DDn   768
#define ROWS  (Bsz*NPIC*SSn)   // 25088
#define QROWS (Bsz*SSn)        // 6272
#define NBat  (Bsz*NPIC)       // 128
#define KPAD  256
#define KVLD  1536             // fused K|V row stride

// ================= device scratch =================
__device__ __align__(1024) __half g_p  [ROWS*DDn];
__device__ __align__(1024) __half g_wt [6*DDn*DDn];   // 0=W1 rowmajor,1-5=transposed Wq,Wk,Wv,Wo1,Wo2
__device__ __align__(1024) __half g_wc [3*DDn*DDn];   // composite (W1Wq)T,(W1Wk)T,(W1Wv)T
__device__ __align__(1024) float  g_bc [3*DDn];       // composite biases q,k,v
__device__ __align__(1024) __half g_q  [QROWS*DDn];
__device__ __align__(1024) __half g_kv [ROWS*KVLD];   // K cols 0..767, V cols 768..1535
__device__ __align__(1024) __half g_vt [NBat*DDn*KPAD];
__device__ __align__(1024) __half g_at [NBat*SSn*KPAD];
__device__ __align__(1024) __half g_wv [ROWS*DDn];
__device__ __align__(1024) __half g_t  [ROWS*DDn];

// ================= helpers =================
__device__ __forceinline__ uint32_t smem_u32(const void* p){
    uint32_t a;
    asm("{ .reg .u64 t; cvta.to.shared.u64 t, %1; cvt.u32.u64 %0, t; }" : "=r"(a) : "l"(p));
    return a;
}
#define SWZ128(o) ((o) ^ (((o) >> 3) & 0x70))

__device__ __forceinline__ void cp16(uint32_t dst, const void* src, int nbytes){
    asm volatile("cp.async.cg.shared.global [%0], [%1], 16, %2;"
                 :: "r"(dst), "l"(src), "r"(nbytes) : "memory");
}
__device__ __forceinline__ void cp_commit(){ asm volatile("cp.async.commit_group;" ::: "memory"); }
__device__ __forceinline__ void cp_wait1(){  asm volatile("cp.async.wait_group 1;" ::: "memory"); }

__device__ __forceinline__ void ldsm4(uint32_t& r0,uint32_t& r1,uint32_t& r2,uint32_t& r3,uint32_t a){
    asm volatile("ldmatrix.sync.aligned.m8n8.x4.shared.b16 {%0,%1,%2,%3}, [%4];"
        : "=r"(r0),"=r"(r1),"=r"(r2),"=r"(r3) : "r"(a));
}
__device__ __forceinline__ void mma16816(float* c, const uint32_t* a, const uint32_t* b){
    asm volatile("mma.sync.aligned.m16n8k16.row.col.f32.f16.f16.f32 "
        "{%0,%1,%2,%3}, {%4,%5,%6,%7}, {%8,%9}, {%0,%1,%2,%3};"
        : "+f"(c[0]),"+f"(c[1]),"+f"(c[2]),"+f"(c[3])
        : "r"(a[0]),"r"(a[1]),"r"(a[2]),"r"(a[3]), "r"(b[0]),"r"(b[1]));
}

// ========== fused prep: patchify + weight convert/transpose + composite bias ==========
#define PATCH_BLK ((ROWS*DDn)/256)          // 75264
#define WPREP_BLK ((6*DDn*DDn)/256)         // 13824
#define BIAS_BLK  9
__global__ void prep_all(const float* __restrict__ x,
                         const float* __restrict__ W1, const float* __restrict__ Wq,
                         const float* __restrict__ Wk, const float* __restrict__ Wv,
                         const float* __restrict__ Wo1, const float* __restrict__ Wo2,
                         const float* __restrict__ b1, const float* __restrict__ bq,
                         const float* __restrict__ bk, const float* __restrict__ bv,
                         __half* __restrict__ p, __half* __restrict__ wt,
                         float* __restrict__ bc)
{
    int b = blockIdx.x;
    int t = threadIdx.x;
    if (b < PATCH_BLK) {
        long long idx = (long long)b * 256 + t;
        int d    = (int)(idx % DDn);
        int rest = (int)(idx / DDn);
        int s    = rest % SSn;
        int pic  = rest / SSn;
        int c  = d >> 8;
        int rm = d & 255;
        int ph = rm >> 4;
        int pw = rm & 15;
        int i = s / HPn, j = s % HPn;
        long long src = (((long long)pic * CCH + c) * Him + (i*PPs + ph)) * Wim + (j*PPs + pw);
        p[idx] = __float2half(x[src]);
        return;
    }
    b -= PATCH_BLK;
    if (b < WPREP_BLK) {
        int idx = b * 256 + t;
        int slot = idx / (DDn*DDn);
        int r    = idx % (DDn*DDn);
        if (slot == 0) { wt[idx] = __float2half(W1[r]); return; }
        int n = r / DDn, k = r % DDn;
        const float* W = (slot == 1) ? Wq : (slot == 2) ? Wk : (slot == 3) ? Wv
                       : (slot == 4) ? Wo1 : Wo2;
        wt[idx] = __float2half(W[k*DDn + n]);
        return;
    }
    b -= WPREP_BLK;
    {
        int idx = b * 256 + t;
        if (idx >= 3*DDn) return;
        int which = idx / DDn, n = idx % DDn;
        const float* W  = (which == 0) ? Wq : (which == 1) ? Wk : Wv;
        const float* bx = (which == 0) ? bq : (which == 1) ? bk : bv;
        float s = bx[n];
        for (int k = 0; k < DDn; k++) s += b1[k] * W[k*DDn + n];
        bc[idx] = s;
    }
}

// ================= V transpose from fused KV (pad 256) =====
__global__ void vtrans_h(const __half* __restrict__ KV, __half* __restrict__ vt)
{
    __shared__ __half tile[32][33];
    int z  = blockIdx.z;
    int d0 = blockIdx.x * 32;
    int s0 = blockIdx.y * 32;
    int tx = threadIdx.x, ty = threadIdx.y;
    for (int sy = ty; sy < 32; sy += 8) {
        int s = s0 + sy, d = d0 + tx;
        tile[sy][tx] = (s < SSn) ? KV[((long long)z*SSn + s)*KVLD + DDn + d]
                                 : __float2half(0.f);
    }
    __syncthreads();
    for (int dy = ty; dy < 32; dy += 8) {
        int d = d0 + dy, s = s0 + tx;
        vt[((long long)z*DDn + d)*KPAD + s] = tile[tx][dy];
    }
}

// ================= mma.sync fp16 GEMM =================
// 128x256 CTA tile, BKt=128 per stage (two 64-k subtiles), 2-stage pipeline.
#define BMt 128
#define BNt 256
#define BKt 128
#define NTHR 256
#define SUBA 16384                  // A subtile: 128 rows * 128B
#define SUBB 32768                  // B subtile: 256 rows * 128B
#define STGSZ (2*SUBA + 2*SUBB)     // 96KB: [A0|A1|B0|B1]
#define NSTG  2
#define DSM   (NSTG*STGSZ + 1024)

__global__ void __launch_bounds__(NTHR)
mm_gemm(const __half* __restrict__ A, const __half* __restrict__ B,
        const float* __restrict__ bias,
        float* __restrict__ Cf, __half* __restrict__ Ch, __half* __restrict__ Smx,
        int M, int Nvalid, int K, int ldA, int ldB, int ldC,
        long long sA, long long sB, long long sC, int zdivA,
        float alpha, int relu, int remapA)
{
    extern __shared__ char dsm[];
    uint32_t dyn  = smem_u32(dsm);
    uint32_t base = (dyn + 1023u) & ~1023u;
    const uint32_t stg[NSTG] = { base, base + STGSZ };

    const int t = threadIdx.x, lane = t & 31, w = t >> 5;
    const int wm = w & 1, wn = w >> 1;          // 2 x 4 warps; warp tile 64x64
    const int z = blockIdx.z;
    const int m0 = blockIdx.y * BMt;
    const int n0 = blockIdx.x * BNt;

    const __half* Az = A + (long long)(z / zdivA) * sA;
    const __half* Bz = B + (long long)z * sB;
    float* Cfz = Cf ? Cf + (long long)z * sC : nullptr;
    __half* Chz = Ch ? Ch + (long long)z * sC : nullptr;
    __half* Smxz = Smx ? Smx + (long long)z * sC : nullptr;

    float acc[4][8][4];
#pragma unroll
    for (int a = 0; a < 4; a++)
#pragma unroll
        for (int b = 0; b < 8; b++)
#pragma unroll
            for (int c = 0; c < 4; c++) acc[a][b][c] = 0.f;

    // ---- hoisted load offsets (all sizes < 2^31 elements) ----
    uint32_t aOff[4], aDst[4]; int aOk[4];
#pragma unroll
    for (int j = 0; j < 4; j++) {
        int flat = t + j*256;
        int row = flat >> 3, cc = flat & 7;
        aDst[j] = SWZ128((uint32_t)(row*128 + cc*16));
        int gr = m0 + row;
        aOk[j] = gr < M;
        long long pr = 0;
        if (aOk[j]) pr = remapA ? (long long)gr + (gr/SSn)*(NPIC*SSn - SSn)
                                : (long long)gr;
        aOff[j] = (uint32_t)(pr * ldA + cc*8);
    }
    uint32_t bOff[8], bDst[8]; int bOk[8];
#pragma unroll
    for (int j = 0; j < 8; j++) {
        int flat = t + j*256;
        int row = flat >> 3, cc = flat & 7;
        bDst[j] = SWZ128((uint32_t)(row*128 + cc*16));
        int gn = n0 + row;
        bOk[j] = gn < Nvalid;
        bOff[j] = (uint32_t)((long long)(bOk[j] ? gn : 0) * ldB + cc*8);
    }

    const int ITERS = K / BKt;   // 6 for K=768, 2 for K=256

#define LOAD_STAGE(ITN, BUF)                                                         \
    {                                                                                \
        uint32_t k0 = (uint32_t)(ITN) * BKt;                                         \
        _Pragma("unroll")                                                            \
        for (int h = 0; h < 2; h++) {                                                \
            _Pragma("unroll")                                                        \
            for (int j = 0; j < 4; j++)                                              \
                cp16(stg[BUF] + h*SUBA + aDst[j],                                    \
                     Az + aOff[j] + k0 + h*64, aOk[j] ? 16 : 0);                     \
            _Pragma("unroll")                                                        \
            for (int j = 0; j < 8; j++)                                              \
                cp16(stg[BUF] + 2*SUBA + h*SUBB + bDst[j],                           \
                     Bz + bOff[j] + k0 + h*64, bOk[j] ? 16 : 0);                     \
        }                                                                            \
    }

    LOAD_STAGE(0, 0); cp_commit();

    const int rl = lane & 15, hh = lane >> 4;

    for (int itn = 0; itn < ITERS; itn++) {
        int buf = itn & 1;
        if (itn + 1 < ITERS) { LOAD_STAGE(itn + 1, (itn + 1) & 1); }
        cp_commit();
        cp_wait1();
        __syncthreads();

        uint32_t sA_ = stg[buf], sB_ = stg[buf] + 2*SUBA;
#pragma unroll
        for (int ks = 0; ks < 8; ks++) {
            int c  = ks*2 + hh;          // 0..15
            int h  = c >> 3;             // k-subtile
            int cl = c & 7;
            uint32_t aS = sA_ + h*SUBA;
            uint32_t bS = sB_ + h*SUBB;
            uint32_t af[4][4], bf[8][2];
#pragma unroll
            for (int mt = 0; mt < 4; mt++) {
                int row = wm*64 + mt*16 + rl;
                uint32_t so = SWZ128((uint32_t)(row*128 + cl*16));
                ldsm4(af[mt][0], af[mt][1], af[mt][2], af[mt][3], aS + so);
            }
#pragma unroll
            for (int bt = 0; bt < 4; bt++) {
                int row = wn*64 + bt*16 + rl;
                uint32_t so = SWZ128((uint32_t)(row*128 + cl*16));
                uint32_t r0, r1, r2, r3;
                ldsm4(r0, r1, r2, r3, bS + so);
                bf[bt*2][0]   = r0;  bf[bt*2][1]   = r2;
                bf[bt*2+1][0] = r1;  bf[bt*2+1][1] = r3;
            }
#pragma unroll
            for (int mt = 0; mt < 4; mt++)
#pragma unroll
                for (int nt = 0; nt < 8; nt++)
                    mma16816(acc[mt][nt], af[mt], bf[nt]);
        }
    }

    const int r0l = lane >> 2, cl2 = (lane & 3) * 2;

    if (Smx) {
        // ---- fused softmax epilogue (CTA holds full rows) ----
        __half* stage = (__half*)(dsm + (base - dyn));
        __syncthreads();
#pragma unroll
        for (int mt = 0; mt < 4; mt++)
#pragma unroll
            for (int nt = 0; nt < 8; nt++) {
                int col = wn*64 + nt*8 + cl2;
#pragma unroll
                for (int half = 0; half < 2; half++) {
                    int r = wm*64 + mt*16 + r0l + half*8;
                    stage[r*256 + col]     = __float2half(acc[mt][nt][half*2 + 0] * alpha);
                    stage[r*256 + col + 1] = __float2half(acc[mt][nt][half*2 + 1] * alpha);
                }
            }
        __syncthreads();
        for (int rr = 0; rr < 16; rr++) {
            int r = w*16 + rr;
            int gr = m0 + r;
            if (gr >= M) continue;
            float v[7];
            float mx = -INFINITY;
#pragma unroll
            for (int i = 0; i < 7; i++) {
                int c = lane + i*32;
                v[i] = (c < SSn) ? __half2float(stage[r*256 + c]) : -INFINITY;
                mx = fmaxf(mx, v[i]);
            }
#pragma unroll
            for (int o = 16; o > 0; o >>= 1) mx = fmaxf(mx, __shfl_xor_sync(0xffffffffu, mx, o));
            float sum = 0.f;
#pragma unroll
            for (int i = 0; i < 7; i++) {
                int c = lane + i*32;
                if (c < SSn) { v[i] = __expf(v[i] - mx); sum += v[i]; } else v[i] = 0.f;
            }
#pragma unroll
            for (int o = 16; o > 0; o >>= 1) sum += __shfl_xor_sync(0xffffffffu, sum, o);
            float inv = 1.f / sum;
            __half* orow = Smxz + (long long)gr * KPAD;
#pragma unroll
            for (int i = 0; i < 8; i++) {
                int c = lane + i*32;
                float val = (i < 7 && c < SSn) ? v[i] * inv : 0.f;
                orow[c] = __float2half(val);
            }
        }
        return;
    }

    // ---- normal epilogue ----
#pragma unroll
    for (int mt = 0; mt < 4; mt++) {
#pragma unroll
        for (int nt = 0; nt < 8; nt++) {
            int gc = n0 + wn*64 + nt*8 + cl2;
#pragma unroll
            for (int half = 0; half < 2; half++) {
                int gr = m0 + wm*64 + mt*16 + r0l + half*8;
                if (gr >= M) continue;
                float v0 = acc[mt][nt][half*2 + 0] * alpha;
                float v1 = acc[mt][nt][half*2 + 1] * alpha;
                if (bias) { v0 += __ldg(bias + gc); v1 += __ldg(bias + gc + 1); }
                if (relu) { v0 = fmaxf(v0, 0.f); v1 = fmaxf(v1, 0.f); }
                long long o = (long long)gr * ldC + gc;
                if (gc < Nvalid) {
                    if (Cfz) Cfz[o] = v0;
                    if (Chz) Chz[o] = __float2half(v0);
                }
                if (gc + 1 < Nvalid) {
                    if (Cfz) Cfz[o+1] = v1;
                    if (Chz) Chz[o+1] = __float2half(v1);
                }
            }
        }
    }
}

// ================= host side =================
static void gemm(const __half* A, const __half* B, const float* bias,
                 float* Cf, __half* Ch, __half* Smx,
                 int M, int Nvalid, int K, int ldA, int ldB, int ldC,
                 long long sA, long long sB, long long sC, int zdivA, int nz,
                 float alpha, int relu, int remapA)
{
    dim3 g((Nvalid + BNt - 1)/BNt, (M + BMt - 1)/BMt, nz);
    mm_gemm<<<g, NTHR, DSM>>>(A, B, bias, Cf, Ch, Smx,
                              M, Nvalid, K, ldA, ldB, ldC, sA, sB, sC,
                              zdivA, alpha, relu, remapA);
}

extern "C" void kernel_launch(void* const* d_in, const int* in_sizes, int n_in,
                              void* d_out, int out_size)
{
    const float* x   = (const float*)d_in[0];
    const float* W1  = (const float*)d_in[1];
    const float* b1  = (const float*)d_in[2];
    const float* Wq  = (const float*)d_in[3];
    const float* bq  = (const float*)d_in[4];
    const float* Wk  = (const float*)d_in[5];
    const float* bk  = (const float*)d_in[6];
    const float* Wv  = (const float*)d_in[7];
    const float* bv  = (const float*)d_in[8];
    const float* Wo1 = (const float*)d_in[9];
    const float* bo1 = (const float*)d_in[10];
    const float* Wo2 = (const float*)d_in[11];
    const float* bo2 = (const float*)d_in[12];
    float* out = (float*)d_out;

    cudaFuncSetAttribute(mm_gemm, cudaFuncAttributeMaxDynamicSharedMemorySize, DSM);

    __half *p,*wt,*wc,*q,*kv,*vt,*at,*wv,*tb;
    float *bc;
    cudaGetSymbolAddress((void**)&p,  g_p);
    cudaGetSymbolAddress((void**)&wt, g_wt);
    cudaGetSymbolAddress((void**)&wc, g_wc);
    cudaGetSymbolAddress((void**)&bc, g_bc);
    cudaGetSymbolAddress((void**)&q,  g_q);
    cudaGetSymbolAddress((void**)&kv, g_kv);
    cudaGetSymbolAddress((void**)&vt, g_vt);
    cudaGetSymbolAddress((void**)&at, g_at);
    cudaGetSymbolAddress((void**)&wv, g_wv);
    cudaGetSymbolAddress((void**)&tb, g_t);

    __half* w1h   = wt + 0*DDn*DDn;   // W1 row-major fp16
    __half* wtqkv = wt + 1*DDn*DDn;   // [WqT;WkT;WvT] stacked (2304 x 768)
    __half* wto1  = wt + 4*DDn*DDn;
    __half* wto2  = wt + 5*DDn*DDn;
    __half* wcq   = wc + 0*DDn*DDn;   // (W1 Wq)^T
    __half* wckv  = wc + 1*DDn*DDn;   // [(W1Wk)T;(W1Wv)T] stacked (1536 x 768)
    float* bcq  = bc + 0*DDn;
    float* bckv = bc + 1*DDn;

    // 1. fused prep: patchify + weight convert/transpose + composite biases
    prep_all<<<PATCH_BLK + WPREP_BLK + BIAS_BLK, 256>>>(
        x, W1, Wq, Wk, Wv, Wo1, Wo2, b1, bq, bk, bv, p, wt, bc);
    // 2. composite weights, one launch: [2304][768] = [WqT;WkT;WvT] @ W1^T
    gemm(wtqkv, w1h, nullptr, nullptr, wc, nullptr,
         3*DDn, DDn, DDn, DDn, DDn, DDn, 0,0,0, 1,1, 1.f, 0, 0);
    // 3. Q = p0 @ Wcq + bcq (remap picture-0 rows of p)
    gemm(p, wcq, bcq, nullptr, q, nullptr,
         QROWS, DDn, DDn, DDn, DDn, DDn, 0,0,0, 1,1, 1.f, 0, 1);
    // 4. K|V = p @ [Wck|Wcv] + [bck|bcv]  (fused, N=1536)
    gemm(p, wckv, bckv, nullptr, kv, nullptr,
         ROWS, KVLD, DDn, DDn, DDn, KVLD, 0,0,0, 1,1, 1.f, 0, 0);
    // 5. V transpose -> Vt [z][768][256]
    {
        dim3 g(DDn/32, KPAD/32, NBat), b(32, 8);
        vtrans_h<<<g, b>>>(kv, vt);
    }
    // 6. attn = softmax(scale * Q @ K^T)  (fused epilogue, batched)
    {
        float scale = 1.f / sqrtf((float)DDn);
        gemm(q, kv, nullptr, nullptr, nullptr, at,
             SSn, SSn, DDn, DDn, KVLD, KPAD,
             (long long)SSn*DDn, (long long)SSn*KVLD, (long long)SSn*KPAD,
             NPIC, NBat, scale, 0, 0);
    }
    // 7. wv = attn @ V (B = Vt)
    gemm(at, vt, nullptr, nullptr, wv, nullptr,
         SSn, DDn, KPAD, KPAD, KPAD, DDn,
         (long long)SSn*KPAD, (long long)DDn*KPAD, (long long)SSn*DDn,
         1, NBat, 1.f, 0, 0);
    // 8. t = relu(wv @ Wo1 + bo1)
    gemm(wv, wto1, bo1, nullptr, tb, nullptr,
         ROWS, DDn, DDn, DDn, DDn, DDn, 0,0,0, 1,1, 1.f, 1, 0);
    // 9. out = t @ Wo2 + bo2
    gemm(tb, wto2, bo2, out, nullptr, nullptr,
         ROWS, DDn, DDn, DDn, DDn, DDn, 0,0,0, 1,1, 1.f, 0, 0);
}